// round 9
// baseline (speedup 1.0000x reference)
#include <cuda_runtime.h>
#include <cstdint>

#define RESP 32
#define RESF 64
#define NP   8192
#define NF   65536
#define CH   128
#define EPSV 1e-5f

// ---- scratch (device globals: allocation-free rule) ----
__device__ int   g_pg[RESP*RESP*RESP];
__device__ float g_h1[NP*CH];
__device__ float g_out1[NF*CH];
__device__ float g_h2[NF*CH];
__device__ float g_M1s[64*CH*CH];   // aggregated conv1 weights, [mat][n][k], tf32-rounded
__device__ float g_W2s[27*CH*CH];   // conv2 weights, [mat][n][k], tf32-rounded
__device__ float g_sum[32], g_sq[32];      // GN2 stats
__device__ float g_ps[32][32], g_pq[32][32];

// ================= helpers =================
__device__ __forceinline__ uint32_t smem_u32(const void* p) {
    uint32_t a;
    asm("{ .reg .u64 t; cvta.to.shared.u64 t, %1; cvt.u32.u64 %0, t; }" : "=r"(a) : "l"(p));
    return a;
}
__device__ __forceinline__ float tf32r(float x) {
    uint32_t u;
    asm("cvt.rna.tf32.f32 %0, %1;" : "=r"(u) : "f"(x));
    return __uint_as_float(u);
}
__device__ __forceinline__ void cp16(uint32_t dst, const void* src, uint32_t ssz) {
    asm volatile("cp.async.cg.shared.global [%0], [%1], 16, %2;" :: "r"(dst), "l"(src), "r"(ssz));
}
__device__ __forceinline__ void cp_commit() { asm volatile("cp.async.commit_group;"); }
#define CP_WAIT(n) asm volatile("cp.async.wait_group %0;" :: "n"(n) : "memory")

__device__ __forceinline__ void ldsm4(uint32_t* r, uint32_t addr) {
    asm volatile("ldmatrix.sync.aligned.m8n8.x4.shared.b16 {%0,%1,%2,%3}, [%4];"
        : "=r"(r[0]), "=r"(r[1]), "=r"(r[2]), "=r"(r[3]) : "r"(addr));
}
__device__ __forceinline__ void mma_tf32(float* d, const uint32_t* a, const uint32_t* b) {
    asm volatile("mma.sync.aligned.m16n8k8.row.col.f32.tf32.tf32.f32 "
        "{%0,%1,%2,%3}, {%4,%5,%6,%7}, {%8,%9}, {%0,%1,%2,%3};"
        : "+f"(d[0]), "+f"(d[1]), "+f"(d[2]), "+f"(d[3])
        : "r"(a[0]), "r"(a[1]), "r"(a[2]), "r"(a[3]), "r"(b[0]), "r"(b[1]));
}

// ================= fused grid build (single block, internal sync) =================
__global__ __launch_bounds__(1024)
void k_grid(const int* __restrict__ coords) {
    int t = threadIdx.x;
    for (int i = t; i < RESP*RESP*RESP; i += 1024) g_pg[i] = -1;
    __syncthreads();
    for (int i = t; i < NP; i += 1024)
        g_pg[(coords[i*3]*RESP + coords[i*3+1])*RESP + coords[i*3+2]] = i;
}

// ================= fused weight prep: M1 aggregate + W2 transpose, tf32 round =================
__global__ void k_prepw(const float* __restrict__ W1, const float* __restrict__ W2) {
    int idx = blockIdx.x * blockDim.x + threadIdx.x;
    if (idx < 64*CH*CH) {
        int m = idx >> 14, rest = idx & 16383;
        int n = rest >> 7, kk = rest & 127;
        int k = m >> 3, j = m & 7;
        int s[3], cnt[3];
#pragma unroll
        for (int a = 0; a < 3; a++) {
            int o  = (k >> (2 - a)) & 1;
            int eb = (j >> (2 - a)) & 1;
            cnt[a] = 1 + (o ^ eb);
            s[a]   = -1 + eb * (1 + o);
        }
        float acc = 0.f;
        for (int d0 = 0; d0 < cnt[0]; d0++)
            for (int d1 = 0; d1 < cnt[1]; d1++)
                for (int d2 = 0; d2 < cnt[2]; d2++) {
                    int k27 = ((s[0]+d0+1)*3 + (s[1]+d1+1))*3 + (s[2]+d2+1);
                    acc += W1[k27*CH*CH + kk*CH + n];
                }
        g_M1s[idx] = tf32r(acc);
    } else if (idx < 91*CH*CH) {
        int i2 = idx - 64*CH*CH;
        int m = i2 >> 14, rest = i2 & 16383;
        int n = rest >> 7, kk = rest & 127;
        g_W2s[i2] = tf32r(W2[m*CH*CH + kk*CH + n]);
    }
}

// ================= GN1: fused stats + normalize + SiLU (block per group) =================
__global__ __launch_bounds__(256)
void k_gn1(const float* __restrict__ feats,
           const float* __restrict__ gamma, const float* __restrict__ beta) {
    int g = blockIdx.x, t = threadIdx.x;
    float s = 0.f, q = 0.f;
    for (int r = t; r < NP; r += 256) {
        float4 v = *reinterpret_cast<const float4*>(feats + r*CH + g*4);
        s += (v.x + v.y) + (v.z + v.w);
        q += (v.x*v.x + v.y*v.y) + (v.z*v.z + v.w*v.w);
    }
    __shared__ float ss[256], sq[256];
    ss[t] = s; sq[t] = q;
    __syncthreads();
    for (int st = 128; st > 0; st >>= 1) {
        if (t < st) { ss[t] += ss[t+st]; sq[t] += sq[t+st]; }
        __syncthreads();
    }
    const float invcnt = 1.f / (NP * 4);
    float mean = ss[0] * invcnt;
    float var  = sq[0] * invcnt - mean * mean;
    float inv  = rsqrtf(var + EPSV);
    float4 ga = *reinterpret_cast<const float4*>(gamma + g*4);
    float4 be = *reinterpret_cast<const float4*>(beta + g*4);
    for (int r = t; r < NP; r += 256) {
        float4 v = *reinterpret_cast<const float4*>(feats + r*CH + g*4);
        float4 o; float y;
        y = (v.x - mean)*inv*ga.x + be.x; o.x = tf32r(y / (1.f + expf(-y)));
        y = (v.y - mean)*inv*ga.y + be.y; o.y = tf32r(y / (1.f + expf(-y)));
        y = (v.z - mean)*inv*ga.z + be.z; o.z = tf32r(y / (1.f + expf(-y)));
        y = (v.w - mean)*inv*ga.w + be.w; o.w = tf32r(y / (1.f + expf(-y)));
        *reinterpret_cast<float4*>(g_h1 + r*CH + g*4) = o;
    }
}

// ================= GN2 stats (two-phase over g_out1) =================
__global__ void k_stats1(int nsl) {
    int g = blockIdx.x, sl = blockIdx.y;
    int per = NF / nsl, r0 = sl * per;
    float s = 0.f, q = 0.f;
    for (int r = r0 + threadIdx.x; r < r0 + per; r += blockDim.x) {
        float4 v = *reinterpret_cast<const float4*>(g_out1 + r*CH + g*4);
        s += (v.x + v.y) + (v.z + v.w);
        q += (v.x*v.x + v.y*v.y) + (v.z*v.z + v.w*v.w);
    }
    __shared__ float ss[256], sq[256];
    ss[threadIdx.x] = s; sq[threadIdx.x] = q;
    __syncthreads();
    for (int st = 128; st > 0; st >>= 1) {
        if (threadIdx.x < st) { ss[threadIdx.x] += ss[threadIdx.x+st]; sq[threadIdx.x] += sq[threadIdx.x+st]; }
        __syncthreads();
    }
    if (threadIdx.x == 0) { g_ps[g][sl] = ss[0]; g_pq[g][sl] = sq[0]; }
}
__global__ void k_stats2(int nsl) {
    int g = blockIdx.x, t = threadIdx.x;
    float s = (t < nsl) ? g_ps[g][t] : 0.f;
    float q = (t < nsl) ? g_pq[g][t] : 0.f;
#pragma unroll
    for (int o = 16; o > 0; o >>= 1) {
        s += __shfl_xor_sync(0xffffffff, s, o);
        q += __shfl_xor_sync(0xffffffff, q, o);
    }
    if (t == 0) { g_sum[g] = s; g_sq[g] = q; }
}
__global__ void k_gnsilu2(const float* __restrict__ gamma, const float* __restrict__ beta) {
    int idx = blockIdx.x * blockDim.x + threadIdx.x;
    if (idx >= NF*32) return;
    int g = idx & 31;
    const float invcnt = 1.f / (NF * 4);
    float mean = g_sum[g] * invcnt;
    float var  = g_sq[g] * invcnt - mean * mean;
    float inv  = rsqrtf(var + EPSV);
    float4 v  = reinterpret_cast<const float4*>(g_out1)[idx];
    float4 ga = reinterpret_cast<const float4*>(gamma)[g];
    float4 be = reinterpret_cast<const float4*>(beta)[g];
    float4 o; float y;
    y = (v.x - mean)*inv*ga.x + be.x; o.x = tf32r(y / (1.f + expf(-y)));
    y = (v.y - mean)*inv*ga.y + be.y; o.y = tf32r(y / (1.f + expf(-y)));
    y = (v.z - mean)*inv*ga.z + be.z; o.z = tf32r(y / (1.f + expf(-y)));
    y = (v.w - mean)*inv*ga.w + be.w; o.w = tf32r(y / (1.f + expf(-y)));
    reinterpret_cast<float4*>(g_h2)[idx] = o;
}

// ================= tf32 mma conv kernels =================
// CTA: 128 rows x 128 cols, 8 warps (4m x 2n), warp tile 32x64.
// 3-stage cp.async pipeline, BK=16, row pitch 20 floats (conflict-free ldmatrix).
// __launch_bounds__(256,3): cap regs at 85 so 3 CTAs/SM fit (occ 21.9% -> ~35%).
#define STG_PITCH 10240          // 128 rows * 80 B
#define ROW_P 80

template<int NTAPS, bool ISC2>
__global__ __launch_bounds__(256, 3)
void k_convmma(const int* __restrict__ coords, const float* __restrict__ bias,
               const float* __restrict__ feats, float* __restrict__ dout) {
    extern __shared__ char dsm[];
    uint32_t smA = smem_u32(dsm);              // 3 * 10240
    uint32_t smB = smA + 3*STG_PITCH;          // 3 * 10240
    int* snb = (int*)(dsm + 6*STG_PITCH);      // NTAPS*128 ints

    const float* hsrc = ISC2 ? g_h2  : g_h1;
    const float* Wp   = ISC2 ? g_W2s : g_M1s;
    float* outp       = ISC2 ? dout  : g_out1;

    int tid = threadIdx.x, lane = tid & 31, wid = tid >> 5;
    int wm = wid & 3, wn = wid >> 2;
    int bx = blockIdx.x, ko = blockIdx.y;
    const int matBase = ISC2 ? 0 : ko*8;

    // ---- neighbor precompute ----
    for (int t = tid; t < NTAPS*128; t += 256) {
        int tap = t >> 7, row = t & 127;
        int nb = -1;
        if (ISC2) {
            int grow = bx*128 + row;
            int pi = grow >> 3, k8 = grow & 7;
            int f0 = 2*coords[pi*3+0] + ((k8 >> 2) & 1) + (tap/9 - 1);
            int f1 = 2*coords[pi*3+1] + ((k8 >> 1) & 1) + ((tap/3) % 3 - 1);
            int f2 = 2*coords[pi*3+2] + (k8 & 1)        + (tap % 3 - 1);
            if ((unsigned)f0 < RESF && (unsigned)f1 < RESF && (unsigned)f2 < RESF) {
                int p = g_pg[((f0 >> 1)*RESP + (f1 >> 1))*RESP + (f2 >> 1)];
                if (p >= 0) nb = p*8 + (((f0 & 1) << 2) | ((f1 & 1) << 1) | (f2 & 1));
            }
        } else {
            int p = bx*128 + row;
            int q0 = coords[p*3+0] + ((ko >> 2) & 1) - 1 + ((tap >> 2) & 1);
            int q1 = coords[p*3+1] + ((ko >> 1) & 1) - 1 + ((tap >> 1) & 1);
            int q2 = coords[p*3+2] + (ko & 1)        - 1 + (tap & 1);
            if ((unsigned)q0 < RESP && (unsigned)q1 < RESP && (unsigned)q2 < RESP)
                nb = g_pg[(q0*RESP + q1)*RESP + q2];
        }
        snb[t] = nb;
    }
    __syncthreads();

    // per-thread loader coords: 2 cp16 for A row, 2 for B row
    const int lrow = tid >> 1, lhalf = tid & 1;

    // per-thread ldmatrix bases (stage-0 absolute; add stage offset later)
    uint32_t Abase = smA + (uint32_t)((wm*32 + ((lane>>3)&1)*8 + (lane&7))*ROW_P + ((lane>>4)&1)*16);
    uint32_t Bbase = smB + (uint32_t)((wn*64 + ((lane>>4)&1)*8 + (lane&7))*ROW_P + ((lane>>3)&1)*16);

    float acc[2][8][4];
#pragma unroll
    for (int mt = 0; mt < 2; mt++)
#pragma unroll
        for (int nt = 0; nt < 8; nt++)
#pragma unroll
            for (int c = 0; c < 4; c++) acc[mt][nt][c] = 0.f;

    const int T = NTAPS * 8;

    // prologue: stages 0,1
#pragma unroll
    for (int s = 0; s < 2; s++) {
        int tap = s >> 3, c0 = (s & 7) * 16;
        int src = snb[tap*128 + lrow];
        uint32_t ssz = src >= 0 ? 16u : 0u;
        const float* ap = hsrc + (src < 0 ? 0 : src)*CH + c0 + lhalf*8;
        uint32_t ad = smA + s*STG_PITCH + lrow*ROW_P + lhalf*32;
        cp16(ad, ap, ssz); cp16(ad + 16, ap + 4, ssz);
        const float* bp = Wp + ((matBase + tap)*128 + lrow)*128 + c0 + lhalf*8;
        uint32_t bd = smB + s*STG_PITCH + lrow*ROW_P + lhalf*32;
        cp16(bd, bp, 16u); cp16(bd + 16, bp + 4, 16u);
        cp_commit();
    }

    int sbuf = 0;
    for (int s = 0; s < T; s++) {
        if (s + 2 < T) CP_WAIT(1); else CP_WAIT(0);
        __syncthreads();
        if (s + 2 < T) {
            int s2 = s + 2;
            int tap = s2 >> 3, c0 = (s2 & 7) * 16;
            int buf2 = sbuf + 2; if (buf2 >= 3) buf2 -= 3;
            int src = snb[tap*128 + lrow];
            uint32_t ssz = src >= 0 ? 16u : 0u;
            const float* ap = hsrc + (src < 0 ? 0 : src)*CH + c0 + lhalf*8;
            uint32_t ad = smA + buf2*STG_PITCH + lrow*ROW_P + lhalf*32;
            cp16(ad, ap, ssz); cp16(ad + 16, ap + 4, ssz);
            const float* bp = Wp + ((matBase + tap)*128 + lrow)*128 + c0 + lhalf*8;
            uint32_t bd = smB + buf2*STG_PITCH + lrow*ROW_P + lhalf*32;
            cp16(bd, bp, 16u); cp16(bd + 16, bp + 4, 16u);
            cp_commit();
        }
        uint32_t ao = sbuf*STG_PITCH, bo = sbuf*STG_PITCH;
#pragma unroll
        for (int ks = 0; ks < 2; ks++) {
            uint32_t kb = ks * 32;   // 8 floats = 32 bytes
            uint32_t a[2][4];
            ldsm4(a[0], Abase + ao + kb);
            ldsm4(a[1], Abase + ao + kb + 16*ROW_P);
            // interleave B-ldsm with consuming MMAs to shorten live ranges (reg cap 85)
#pragma unroll
            for (int p = 0; p < 4; p++) {
                uint32_t b[4];
                ldsm4(b, Bbase + bo + kb + p*16*ROW_P);
#pragma unroll
                for (int mt = 0; mt < 2; mt++) {
                    mma_tf32(acc[mt][p*2 + 0], a[mt], &b[0]);
                    mma_tf32(acc[mt][p*2 + 1], a[mt], &b[2]);
                }
            }
        }
        sbuf++; if (sbuf == 3) sbuf = 0;
    }

    // ---- epilogue: direct register -> gmem, fused bias (+residual) ----
#pragma unroll
    for (int mt = 0; mt < 2; mt++) {
        int rl = wm*32 + mt*16 + (lane >> 2);
#pragma unroll
        for (int half = 0; half < 2; half++) {
            int row = rl + half*8;
            int orow, prow;
            if (ISC2) { orow = bx*128 + row; prow = orow >> 3; }
            else      { orow = (bx*128 + row)*8 + ko; prow = -1; }
#pragma unroll
            for (int nt = 0; nt < 8; nt++) {
                int col = wn*64 + nt*8 + (lane & 3)*2;
                float2 bb = *reinterpret_cast<const float2*>(bias + col);
                float vx = acc[mt][nt][half*2 + 0] + bb.x;
                float vy = acc[mt][nt][half*2 + 1] + bb.y;
                if (ISC2) {
                    float2 rr = *reinterpret_cast<const float2*>(feats + prow*CH + col);
                    vx += rr.x; vy += rr.y;
                }
                float2 o; o.x = vx; o.y = vy;
                *reinterpret_cast<float2*>(outp + orow*CH + col) = o;
            }
        }
    }
}

// ================= launch =================
extern "C" void kernel_launch(void* const* d_in, const int* in_sizes, int n_in,
                              void* d_out, int out_size) {
    const float* feats  = (const float*)d_in[0];
    const float* gamma1 = (const float*)d_in[1];
    const float* beta1  = (const float*)d_in[2];
    const float* W1     = (const float*)d_in[3];
    const float* b1     = (const float*)d_in[4];
    const float* gamma2 = (const float*)d_in[5];
    const float* beta2  = (const float*)d_in[6];
    const float* W2     = (const float*)d_in[7];
    const float* b2     = (const float*)d_in[8];
    const int*   coords = (const int*)d_in[9];
    float* out = (float*)d_out;

    const int smem1 = 6*STG_PITCH + 8*128*4;    // 65536
    const int smem2 = 6*STG_PITCH + 27*128*4;   // 75264
    cudaFuncSetAttribute(k_convmma<8,false>, cudaFuncAttributeMaxDynamicSharedMemorySize, smem1);
    cudaFuncSetAttribute(k_convmma<27,true>, cudaFuncAttributeMaxDynamicSharedMemorySize, smem2);

    // (0) grid build (fused init+scatter)
    k_grid<<<1, 1024>>>(coords);
    // (1) weight prep (fused M1 aggregate + W2 transpose)
    k_prepw<<<(91*CH*CH + 255)/256, 256>>>(W1, W2);
    // (2) GN1 fused stats+norm+SiLU -> g_h1
    k_gn1<<<32, 256>>>(feats, gamma1, beta1);
    // (3) conv1 (parent-level, aggregated taps) -> g_out1   [ncu-profiled slot]
    k_convmma<8,false><<<dim3(64, 8), 256, smem1>>>(coords, b1, nullptr, nullptr);
    // (4,5) GN2 stats two-phase
    k_stats1<<<dim3(32, 32), 256>>>(32);
    k_stats2<<<32, 32>>>(32);
    // (6) GN2 normalize + SiLU -> g_h2
    k_gnsilu2<<<(NF*32 + 255)/256, 256>>>(gamma2, beta2);
    // (7) conv2 (fine-level, 27 taps) + bias + residual -> out
    k_convmma<27,true><<<512, 256, smem2>>>(coords, b2, feats, out);
}

// round 10
// speedup vs baseline: 1.7332x; 1.7332x over previous
#include <cuda_runtime.h>
#include <cstdint>

#define RESP 32
#define RESF 64
#define NP   8192
#define NF   65536
#define CH   128
#define EPSV 1e-5f

// ---- scratch (device globals: allocation-free rule) ----
__device__ int   g_pg[RESP*RESP*RESP];
__device__ float g_h1[NP*CH];
__device__ float g_out1[NF*CH];
__device__ float g_h2[NF*CH];
__device__ float g_M1s[64*CH*CH];   // aggregated conv1 weights, [mat][n][k], tf32-rounded
__device__ float g_W2s[27*CH*CH];   // conv2 weights, [mat][n][k], tf32-rounded
__device__ float g_sum[32], g_sq[32];      // GN2 stats
__device__ float g_ps[32][32], g_pq[32][32];

// ================= helpers =================
__device__ __forceinline__ uint32_t smem_u32(const void* p) {
    uint32_t a;
    asm("{ .reg .u64 t; cvta.to.shared.u64 t, %1; cvt.u32.u64 %0, t; }" : "=r"(a) : "l"(p));
    return a;
}
__device__ __forceinline__ float tf32r(float x) {
    uint32_t u;
    asm("cvt.rna.tf32.f32 %0, %1;" : "=r"(u) : "f"(x));
    return __uint_as_float(u);
}
__device__ __forceinline__ void cp16(uint32_t dst, const void* src, uint32_t ssz) {
    asm volatile("cp.async.cg.shared.global [%0], [%1], 16, %2;" :: "r"(dst), "l"(src), "r"(ssz));
}
__device__ __forceinline__ void cp_commit() { asm volatile("cp.async.commit_group;"); }
#define CP_WAIT(n) asm volatile("cp.async.wait_group %0;" :: "n"(n) : "memory")

__device__ __forceinline__ void ldsm4(uint32_t* r, uint32_t addr) {
    asm volatile("ldmatrix.sync.aligned.m8n8.x4.shared.b16 {%0,%1,%2,%3}, [%4];"
        : "=r"(r[0]), "=r"(r[1]), "=r"(r[2]), "=r"(r[3]) : "r"(addr));
}
__device__ __forceinline__ void mma_tf32(float* d, const uint32_t* a, const uint32_t* b) {
    asm volatile("mma.sync.aligned.m16n8k8.row.col.f32.tf32.tf32.f32 "
        "{%0,%1,%2,%3}, {%4,%5,%6,%7}, {%8,%9}, {%0,%1,%2,%3};"
        : "+f"(d[0]), "+f"(d[1]), "+f"(d[2]), "+f"(d[3])
        : "r"(a[0]), "r"(a[1]), "r"(a[2]), "r"(a[3]), "r"(b[0]), "r"(b[1]));
}

// ================= fused grid build (single block, internal sync) =================
__global__ __launch_bounds__(1024)
void k_grid(const int* __restrict__ coords) {
    int t = threadIdx.x;
    for (int i = t; i < RESP*RESP*RESP; i += 1024) g_pg[i] = -1;
    __syncthreads();
    for (int i = t; i < NP; i += 1024)
        g_pg[(coords[i*3]*RESP + coords[i*3+1])*RESP + coords[i*3+2]] = i;
}

// ================= fused weight prep: M1 aggregate + W2 transpose, tf32 round =================
__global__ void k_prepw(const float* __restrict__ W1, const float* __restrict__ W2) {
    int idx = blockIdx.x * blockDim.x + threadIdx.x;
    if (idx < 64*CH*CH) {
        int m = idx >> 14, rest = idx & 16383;
        int n = rest >> 7, kk = rest & 127;
        int k = m >> 3, j = m & 7;
        int s[3], cnt[3];
#pragma unroll
        for (int a = 0; a < 3; a++) {
            int o  = (k >> (2 - a)) & 1;
            int eb = (j >> (2 - a)) & 1;
            cnt[a] = 1 + (o ^ eb);
            s[a]   = -1 + eb * (1 + o);
        }
        float acc = 0.f;
        for (int d0 = 0; d0 < cnt[0]; d0++)
            for (int d1 = 0; d1 < cnt[1]; d1++)
                for (int d2 = 0; d2 < cnt[2]; d2++) {
                    int k27 = ((s[0]+d0+1)*3 + (s[1]+d1+1))*3 + (s[2]+d2+1);
                    acc += W1[k27*CH*CH + kk*CH + n];
                }
        g_M1s[idx] = tf32r(acc);
    } else if (idx < 91*CH*CH) {
        int i2 = idx - 64*CH*CH;
        int m = i2 >> 14, rest = i2 & 16383;
        int n = rest >> 7, kk = rest & 127;
        g_W2s[i2] = tf32r(W2[m*CH*CH + kk*CH + n]);
    }
}

// ================= GN1: fused stats + normalize + SiLU (block per group) =================
__global__ __launch_bounds__(256)
void k_gn1(const float* __restrict__ feats,
           const float* __restrict__ gamma, const float* __restrict__ beta) {
    int g = blockIdx.x, t = threadIdx.x;
    float s = 0.f, q = 0.f;
    for (int r = t; r < NP; r += 256) {
        float4 v = *reinterpret_cast<const float4*>(feats + r*CH + g*4);
        s += (v.x + v.y) + (v.z + v.w);
        q += (v.x*v.x + v.y*v.y) + (v.z*v.z + v.w*v.w);
    }
    __shared__ float ss[256], sq[256];
    ss[t] = s; sq[t] = q;
    __syncthreads();
    for (int st = 128; st > 0; st >>= 1) {
        if (t < st) { ss[t] += ss[t+st]; sq[t] += sq[t+st]; }
        __syncthreads();
    }
    const float invcnt = 1.f / (NP * 4);
    float mean = ss[0] * invcnt;
    float var  = sq[0] * invcnt - mean * mean;
    float inv  = rsqrtf(var + EPSV);
    float4 ga = *reinterpret_cast<const float4*>(gamma + g*4);
    float4 be = *reinterpret_cast<const float4*>(beta + g*4);
    for (int r = t; r < NP; r += 256) {
        float4 v = *reinterpret_cast<const float4*>(feats + r*CH + g*4);
        float4 o; float y;
        y = (v.x - mean)*inv*ga.x + be.x; o.x = tf32r(y / (1.f + expf(-y)));
        y = (v.y - mean)*inv*ga.y + be.y; o.y = tf32r(y / (1.f + expf(-y)));
        y = (v.z - mean)*inv*ga.z + be.z; o.z = tf32r(y / (1.f + expf(-y)));
        y = (v.w - mean)*inv*ga.w + be.w; o.w = tf32r(y / (1.f + expf(-y)));
        *reinterpret_cast<float4*>(g_h1 + r*CH + g*4) = o;
    }
}

// ================= GN2 stats (two-phase over g_out1) =================
__global__ void k_stats1(int nsl) {
    int g = blockIdx.x, sl = blockIdx.y;
    int per = NF / nsl, r0 = sl * per;
    float s = 0.f, q = 0.f;
    for (int r = r0 + threadIdx.x; r < r0 + per; r += blockDim.x) {
        float4 v = *reinterpret_cast<const float4*>(g_out1 + r*CH + g*4);
        s += (v.x + v.y) + (v.z + v.w);
        q += (v.x*v.x + v.y*v.y) + (v.z*v.z + v.w*v.w);
    }
    __shared__ float ss[256], sq[256];
    ss[threadIdx.x] = s; sq[threadIdx.x] = q;
    __syncthreads();
    for (int st = 128; st > 0; st >>= 1) {
        if (threadIdx.x < st) { ss[threadIdx.x] += ss[threadIdx.x+st]; sq[threadIdx.x] += sq[threadIdx.x+st]; }
        __syncthreads();
    }
    if (threadIdx.x == 0) { g_ps[g][sl] = ss[0]; g_pq[g][sl] = sq[0]; }
}
__global__ void k_stats2(int nsl) {
    int g = blockIdx.x, t = threadIdx.x;
    float s = (t < nsl) ? g_ps[g][t] : 0.f;
    float q = (t < nsl) ? g_pq[g][t] : 0.f;
#pragma unroll
    for (int o = 16; o > 0; o >>= 1) {
        s += __shfl_xor_sync(0xffffffff, s, o);
        q += __shfl_xor_sync(0xffffffff, q, o);
    }
    if (t == 0) { g_sum[g] = s; g_sq[g] = q; }
}
__global__ void k_gnsilu2(const float* __restrict__ gamma, const float* __restrict__ beta) {
    int idx = blockIdx.x * blockDim.x + threadIdx.x;
    if (idx >= NF*32) return;
    int g = idx & 31;
    const float invcnt = 1.f / (NF * 4);
    float mean = g_sum[g] * invcnt;
    float var  = g_sq[g] * invcnt - mean * mean;
    float inv  = rsqrtf(var + EPSV);
    float4 v  = reinterpret_cast<const float4*>(g_out1)[idx];
    float4 ga = reinterpret_cast<const float4*>(gamma)[g];
    float4 be = reinterpret_cast<const float4*>(beta)[g];
    float4 o; float y;
    y = (v.x - mean)*inv*ga.x + be.x; o.x = tf32r(y / (1.f + expf(-y)));
    y = (v.y - mean)*inv*ga.y + be.y; o.y = tf32r(y / (1.f + expf(-y)));
    y = (v.z - mean)*inv*ga.z + be.z; o.z = tf32r(y / (1.f + expf(-y)));
    y = (v.w - mean)*inv*ga.w + be.w; o.w = tf32r(y / (1.f + expf(-y)));
    reinterpret_cast<float4*>(g_h2)[idx] = o;
}

// ================= tf32 mma conv kernels =================
// CTA 128x128, 8 warps (4m x 2n), warp tile 32x64 (R8-validated shape).
// BK=32 stages, XOR-swizzled 128B-pitch tiles, 3-stage cp.async pipeline.
// Stage boundaries halve vs BK=16 (conv1 64->32, conv2 216->108).
#define STG_SZ 32768         // A 16KB + B 16KB per stage

template<int NTAPS, bool ISC2>
__global__ __launch_bounds__(256)
void k_convmma(const int* __restrict__ coords, const float* __restrict__ bias,
               const float* __restrict__ feats, float* __restrict__ dout) {
    extern __shared__ char dsm[];
    uint32_t smS = smem_u32(dsm);
    int* snb = (int*)(dsm + 3*STG_SZ);

    const float* hsrc = ISC2 ? g_h2  : g_h1;
    const float* Wp   = ISC2 ? g_W2s : g_M1s;
    float* outp       = ISC2 ? dout  : g_out1;

    int tid = threadIdx.x, lane = tid & 31, wid = tid >> 5;
    int wm = wid & 3, wn = wid >> 2;
    int bx = blockIdx.x, ko = blockIdx.y;
    const int matBase = ISC2 ? 0 : ko*8;

    // ---- neighbor precompute ----
    for (int t = tid; t < NTAPS*128; t += 256) {
        int tap = t >> 7, row = t & 127;
        int nb = -1;
        if (ISC2) {
            int grow = bx*128 + row;
            int pi = grow >> 3, k8 = grow & 7;
            int f0 = 2*coords[pi*3+0] + ((k8 >> 2) & 1) + (tap/9 - 1);
            int f1 = 2*coords[pi*3+1] + ((k8 >> 1) & 1) + ((tap/3) % 3 - 1);
            int f2 = 2*coords[pi*3+2] + (k8 & 1)        + (tap % 3 - 1);
            if ((unsigned)f0 < RESF && (unsigned)f1 < RESF && (unsigned)f2 < RESF) {
                int p = g_pg[((f0 >> 1)*RESP + (f1 >> 1))*RESP + (f2 >> 1)];
                if (p >= 0) nb = p*8 + (((f0 & 1) << 2) | ((f1 & 1) << 1) | (f2 & 1));
            }
        } else {
            int p = bx*128 + row;
            int q0 = coords[p*3+0] + ((ko >> 2) & 1) - 1 + ((tap >> 2) & 1);
            int q1 = coords[p*3+1] + ((ko >> 1) & 1) - 1 + ((tap >> 1) & 1);
            int q2 = coords[p*3+2] + (ko & 1)        - 1 + (tap & 1);
            if ((unsigned)q0 < RESP && (unsigned)q1 < RESP && (unsigned)q2 < RESP)
                nb = g_pg[(q0*RESP + q1)*RESP + q2];
        }
        snb[t] = nb;
    }
    __syncthreads();

    // loader: 2 threads/row, each 4x16B of A and 4x16B of B (per stage row = 32 floats)
    const int lrow = tid >> 1, lhalf = tid & 1;
    const int lrx = lrow & 7;

    // per-lane ldmatrix constants
    const int laneAr = (lane & 7) + ((lane >> 3) & 1)*8;
    const int laneAc = (lane >> 4) & 1;
    const int laneBr = (lane & 7) + ((lane >> 4) & 1)*8;
    const int laneBc = (lane >> 3) & 1;
    uint32_t offA[2], offB[4]; int rxA[2], rxB[4];
#pragma unroll
    for (int i = 0; i < 2; i++) {
        int rA = wm*32 + i*16 + laneAr;
        offA[i] = (uint32_t)rA * 128u; rxA[i] = rA & 7;
    }
#pragma unroll
    for (int i = 0; i < 4; i++) {
        int rB = wn*64 + i*16 + laneBr;
        offB[i] = 16384u + (uint32_t)rB * 128u; rxB[i] = rB & 7;
    }

    float acc[2][8][4];
#pragma unroll
    for (int mt = 0; mt < 2; mt++)
#pragma unroll
        for (int nt = 0; nt < 8; nt++)
#pragma unroll
            for (int c = 0; c < 4; c++) acc[mt][nt][c] = 0.f;

    const int T = NTAPS * 4;

#define LOAD_STAGE(S, BUF) do { \
        int tap_ = (S) >> 2, c0_ = ((S) & 3) * 32; \
        int src_ = snb[tap_*128 + lrow]; \
        uint32_t ssz_ = src_ >= 0 ? 16u : 0u; \
        const float* ap_ = hsrc + (src_ < 0 ? 0 : src_)*CH + c0_; \
        const float* bp_ = Wp + ((matBase + tap_)*128 + lrow)*128 + c0_; \
        uint32_t ad_ = smS + (BUF)*STG_SZ + (uint32_t)lrow*128u; \
        uint32_t bd_ = ad_ + 16384u; \
        _Pragma("unroll") \
        for (int i_ = 0; i_ < 4; i_++) { \
            int c_ = lhalf*4 + i_; \
            uint32_t sw_ = (uint32_t)((c_ ^ lrx) << 4); \
            cp16(ad_ + sw_, ap_ + c_*4, ssz_); \
            cp16(bd_ + sw_, bp_ + c_*4, 16u); \
        } \
        cp_commit(); \
    } while (0)

    LOAD_STAGE(0, 0);
    LOAD_STAGE(1, 1);

    int sbuf = 0;
    for (int s = 0; s < T; s++) {
        if (s + 2 < T) CP_WAIT(1); else CP_WAIT(0);
        __syncthreads();
        if (s + 2 < T) {
            int buf2 = sbuf + 2; if (buf2 >= 3) buf2 -= 3;
            LOAD_STAGE(s + 2, buf2);
        }
        uint32_t stg = smS + (uint32_t)sbuf*STG_SZ;
#pragma unroll
        for (int ks = 0; ks < 4; ks++) {
            int cA = ks*2 + laneAc, cB = ks*2 + laneBc;
            uint32_t a[2][4];
            ldsm4(a[0], stg + offA[0] + (uint32_t)((cA ^ rxA[0]) << 4));
            ldsm4(a[1], stg + offA[1] + (uint32_t)((cA ^ rxA[1]) << 4));
            uint32_t b[4][4];
#pragma unroll
            for (int p = 0; p < 4; p++)
                ldsm4(b[p], stg + offB[p] + (uint32_t)((cB ^ rxB[p]) << 4));
#pragma unroll
            for (int mt = 0; mt < 2; mt++)
#pragma unroll
                for (int nt = 0; nt < 8; nt++)
                    mma_tf32(acc[mt][nt], a[mt], b[nt >> 1] + (nt & 1)*2);
        }
        sbuf++; if (sbuf == 3) sbuf = 0;
    }
#undef LOAD_STAGE

    // ---- epilogue: direct register -> gmem, fused bias (+residual) ----
#pragma unroll
    for (int mt = 0; mt < 2; mt++) {
        int rl = wm*32 + mt*16 + (lane >> 2);
#pragma unroll
        for (int half = 0; half < 2; half++) {
            int row = rl + half*8;
            int orow, prow;
            if (ISC2) { orow = bx*128 + row; prow = orow >> 3; }
            else      { orow = (bx*128 + row)*8 + ko; prow = -1; }
#pragma unroll
            for (int nt = 0; nt < 8; nt++) {
                int col = wn*64 + nt*8 + (lane & 3)*2;
                float2 bb = *reinterpret_cast<const float2*>(bias + col);
                float vx = acc[mt][nt][half*2 + 0] + bb.x;
                float vy = acc[mt][nt][half*2 + 1] + bb.y;
                if (ISC2) {
                    float2 rr = *reinterpret_cast<const float2*>(feats + prow*CH + col);
                    vx += rr.x; vy += rr.y;
                }
                float2 o; o.x = vx; o.y = vy;
                *reinterpret_cast<float2*>(outp + orow*CH + col) = o;
            }
        }
    }
}

// ================= launch =================
extern "C" void kernel_launch(void* const* d_in, const int* in_sizes, int n_in,
                              void* d_out, int out_size) {
    const float* feats  = (const float*)d_in[0];
    const float* gamma1 = (const float*)d_in[1];
    const float* beta1  = (const float*)d_in[2];
    const float* W1     = (const float*)d_in[3];
    const float* b1     = (const float*)d_in[4];
    const float* gamma2 = (const float*)d_in[5];
    const float* beta2  = (const float*)d_in[6];
    const float* W2     = (const float*)d_in[7];
    const float* b2     = (const float*)d_in[8];
    const int*   coords = (const int*)d_in[9];
    float* out = (float*)d_out;

    const int smem1 = 3*STG_SZ + 8*128*4;    // 102400
    const int smem2 = 3*STG_SZ + 27*128*4;   // 112128
    cudaFuncSetAttribute(k_convmma<8,false>, cudaFuncAttributeMaxDynamicSharedMemorySize, smem1);
    cudaFuncSetAttribute(k_convmma<27,true>, cudaFuncAttributeMaxDynamicSharedMemorySize, smem2);

    // (0) grid build (fused init+scatter)
    k_grid<<<1, 1024>>>(coords);
    // (1) weight prep (fused M1 aggregate + W2 transpose)
    k_prepw<<<(91*CH*CH + 255)/256, 256>>>(W1, W2);
    // (2) GN1 fused stats+norm+SiLU -> g_h1
    k_gn1<<<32, 256>>>(feats, gamma1, beta1);
    // (3) conv1 (parent-level, aggregated taps) -> g_out1   [ncu-profiled slot]
    k_convmma<8,false><<<dim3(64, 8), 256, smem1>>>(coords, b1, nullptr, nullptr);
    // (4,5) GN2 stats two-phase
    k_stats1<<<dim3(32, 32), 256>>>(32);
    k_stats2<<<32, 32>>>(32);
    // (6) GN2 normalize + SiLU -> g_h2
    k_gnsilu2<<<(NF*32 + 255)/256, 256>>>(gamma2, beta2);
    // (7) conv2 (fine-level, 27 taps) + bias + residual -> out
    k_convmma<27,true><<<512, 256, smem2>>>(coords, b2, feats, out);
}

// round 11
// speedup vs baseline: 3.0000x; 1.7309x over previous
#include <cuda_runtime.h>
#include <cuda_fp16.h>
#include <cstdint>

#define RESP 32
#define RESF 64
#define NP   8192
#define NF   65536
#define CH   128
#define EPSV 1e-5f

// ---- scratch (device globals: allocation-free rule) ----
__device__ int    g_pg[RESP*RESP*RESP];
__device__ __half g_h1[NP*CH];
__device__ float  g_out1[NF*CH];
__device__ __half g_h2[NF*CH];
__device__ __half g_M1h[64*CH*CH];   // aggregated conv1 weights, [mat][n][k], fp16
__device__ __half g_W2h[27*CH*CH];   // conv2 weights, [mat][n][k], fp16
__device__ float  g_sum[32], g_sq[32];      // GN2 stats
__device__ float  g_ps[32][32], g_pq[32][32];

// ================= helpers =================
__device__ __forceinline__ uint32_t smem_u32(const void* p) {
    uint32_t a;
    asm("{ .reg .u64 t; cvta.to.shared.u64 t, %1; cvt.u32.u64 %0, t; }" : "=r"(a) : "l"(p));
    return a;
}
__device__ __forceinline__ void cp16(uint32_t dst, const void* src, uint32_t ssz) {
    asm volatile("cp.async.cg.shared.global [%0], [%1], 16, %2;" :: "r"(dst), "l"(src), "r"(ssz));
}
__device__ __forceinline__ void cp_commit() { asm volatile("cp.async.commit_group;"); }
#define CP_WAIT(n) asm volatile("cp.async.wait_group %0;" :: "n"(n) : "memory")

__device__ __forceinline__ void ldsm4(uint32_t* r, uint32_t addr) {
    asm volatile("ldmatrix.sync.aligned.m8n8.x4.shared.b16 {%0,%1,%2,%3}, [%4];"
        : "=r"(r[0]), "=r"(r[1]), "=r"(r[2]), "=r"(r[3]) : "r"(addr));
}
// m16n8k16 fp16 MMA, fp32 accumulate
__device__ __forceinline__ void mma_f16(float* d, const uint32_t* a, const uint32_t* b) {
    asm volatile("mma.sync.aligned.m16n8k16.row.col.f32.f16.f16.f32 "
        "{%0,%1,%2,%3}, {%4,%5,%6,%7}, {%8,%9}, {%0,%1,%2,%3};"
        : "+f"(d[0]), "+f"(d[1]), "+f"(d[2]), "+f"(d[3])
        : "r"(a[0]), "r"(a[1]), "r"(a[2]), "r"(a[3]), "r"(b[0]), "r"(b[1]));
}
__device__ __forceinline__ void store_h4(__half* dst, float x, float y, float z, float w) {
    __half2 p0 = __floats2half2_rn(x, y);
    __half2 p1 = __floats2half2_rn(z, w);
    uint2 u;
    u.x = *reinterpret_cast<uint32_t*>(&p0);
    u.y = *reinterpret_cast<uint32_t*>(&p1);
    *reinterpret_cast<uint2*>(dst) = u;
}

// ================= fused grid build =================
__global__ __launch_bounds__(1024)
void k_grid(const int* __restrict__ coords) {
    int t = threadIdx.x;
    for (int i = t; i < RESP*RESP*RESP; i += 1024) g_pg[i] = -1;
    __syncthreads();
    for (int i = t; i < NP; i += 1024)
        g_pg[(coords[i*3]*RESP + coords[i*3+1])*RESP + coords[i*3+2]] = i;
}

// ================= fused weight prep (fp16 output, [mat][n][k]) =================
__global__ void k_prepw(const float* __restrict__ W1, const float* __restrict__ W2) {
    int idx = blockIdx.x * blockDim.x + threadIdx.x;
    if (idx < 64*CH*CH) {
        int m = idx >> 14, rest = idx & 16383;
        int n = rest >> 7, kk = rest & 127;
        int k = m >> 3, j = m & 7;
        int s[3], cnt[3];
#pragma unroll
        for (int a = 0; a < 3; a++) {
            int o  = (k >> (2 - a)) & 1;
            int eb = (j >> (2 - a)) & 1;
            cnt[a] = 1 + (o ^ eb);
            s[a]   = -1 + eb * (1 + o);
        }
        float acc = 0.f;
        for (int d0 = 0; d0 < cnt[0]; d0++)
            for (int d1 = 0; d1 < cnt[1]; d1++)
                for (int d2 = 0; d2 < cnt[2]; d2++) {
                    int k27 = ((s[0]+d0+1)*3 + (s[1]+d1+1))*3 + (s[2]+d2+1);
                    acc += W1[k27*CH*CH + kk*CH + n];
                }
        g_M1h[idx] = __float2half_rn(acc);
    } else if (idx < 91*CH*CH) {
        int i2 = idx - 64*CH*CH;
        int m = i2 >> 14, rest = i2 & 16383;
        int n = rest >> 7, kk = rest & 127;
        g_W2h[i2] = __float2half_rn(W2[m*CH*CH + kk*CH + n]);
    }
}

// ================= GN1: fused stats + normalize + SiLU -> fp16 =================
__global__ __launch_bounds__(256)
void k_gn1(const float* __restrict__ feats,
           const float* __restrict__ gamma, const float* __restrict__ beta) {
    int g = blockIdx.x, t = threadIdx.x;
    float s = 0.f, q = 0.f;
    for (int r = t; r < NP; r += 256) {
        float4 v = *reinterpret_cast<const float4*>(feats + r*CH + g*4);
        s += (v.x + v.y) + (v.z + v.w);
        q += (v.x*v.x + v.y*v.y) + (v.z*v.z + v.w*v.w);
    }
    __shared__ float ss[256], sq[256];
    ss[t] = s; sq[t] = q;
    __syncthreads();
    for (int st = 128; st > 0; st >>= 1) {
        if (t < st) { ss[t] += ss[t+st]; sq[t] += sq[t+st]; }
        __syncthreads();
    }
    const float invcnt = 1.f / (NP * 4);
    float mean = ss[0] * invcnt;
    float var  = sq[0] * invcnt - mean * mean;
    float inv  = rsqrtf(var + EPSV);
    float4 ga = *reinterpret_cast<const float4*>(gamma + g*4);
    float4 be = *reinterpret_cast<const float4*>(beta + g*4);
    for (int r = t; r < NP; r += 256) {
        float4 v = *reinterpret_cast<const float4*>(feats + r*CH + g*4);
        float y, ox, oy, oz, ow;
        y = (v.x - mean)*inv*ga.x + be.x; ox = y / (1.f + expf(-y));
        y = (v.y - mean)*inv*ga.y + be.y; oy = y / (1.f + expf(-y));
        y = (v.z - mean)*inv*ga.z + be.z; oz = y / (1.f + expf(-y));
        y = (v.w - mean)*inv*ga.w + be.w; ow = y / (1.f + expf(-y));
        store_h4(g_h1 + r*CH + g*4, ox, oy, oz, ow);
    }
}

// ================= GN2 stats (two-phase over fp32 g_out1) =================
__global__ void k_stats1(int nsl) {
    int g = blockIdx.x, sl = blockIdx.y;
    int per = NF / nsl, r0 = sl * per;
    float s = 0.f, q = 0.f;
    for (int r = r0 + threadIdx.x; r < r0 + per; r += blockDim.x) {
        float4 v = *reinterpret_cast<const float4*>(g_out1 + r*CH + g*4);
        s += (v.x + v.y) + (v.z + v.w);
        q += (v.x*v.x + v.y*v.y) + (v.z*v.z + v.w*v.w);
    }
    __shared__ float ss[256], sq[256];
    ss[threadIdx.x] = s; sq[threadIdx.x] = q;
    __syncthreads();
    for (int st = 128; st > 0; st >>= 1) {
        if (threadIdx.x < st) { ss[threadIdx.x] += ss[threadIdx.x+st]; sq[threadIdx.x] += sq[threadIdx.x+st]; }
        __syncthreads();
    }
    if (threadIdx.x == 0) { g_ps[g][sl] = ss[0]; g_pq[g][sl] = sq[0]; }
}
__global__ void k_stats2(int nsl) {
    int g = blockIdx.x, t = threadIdx.x;
    float s = (t < nsl) ? g_ps[g][t] : 0.f;
    float q = (t < nsl) ? g_pq[g][t] : 0.f;
#pragma unroll
    for (int o = 16; o > 0; o >>= 1) {
        s += __shfl_xor_sync(0xffffffff, s, o);
        q += __shfl_xor_sync(0xffffffff, q, o);
    }
    if (t == 0) { g_sum[g] = s; g_sq[g] = q; }
}
__global__ void k_gnsilu2(const float* __restrict__ gamma, const float* __restrict__ beta) {
    int idx = blockIdx.x * blockDim.x + threadIdx.x;
    if (idx >= NF*32) return;
    int g = idx & 31;
    const float invcnt = 1.f / (NF * 4);
    float mean = g_sum[g] * invcnt;
    float var  = g_sq[g] * invcnt - mean * mean;
    float inv  = rsqrtf(var + EPSV);
    float4 v  = reinterpret_cast<const float4*>(g_out1)[idx];
    float4 ga = reinterpret_cast<const float4*>(gamma)[g];
    float4 be = reinterpret_cast<const float4*>(beta)[g];
    float y, ox, oy, oz, ow;
    y = (v.x - mean)*inv*ga.x + be.x; ox = y / (1.f + expf(-y));
    y = (v.y - mean)*inv*ga.y + be.y; oy = y / (1.f + expf(-y));
    y = (v.z - mean)*inv*ga.z + be.z; oz = y / (1.f + expf(-y));
    y = (v.w - mean)*inv*ga.w + be.w; ow = y / (1.f + expf(-y));
    store_h4(g_h2 + idx*4, ox, oy, oz, ow);
}

// ================= fp16 mma conv kernels =================
// CTA 128x128, 8 warps (4m x 2n), warp tile 32x64.
// BK=64 channels per stage (128B fp16 rows), XOR-swizzled, 3-stage cp.async.
// m16n8k16 fp16 MMA, fp32 accumulate: 2x FLOP/instr vs tf32, same 11-bit mantissa.
#define STG_SZ 32768         // A 16KB + B 16KB per stage

template<int NTAPS, bool ISC2>
__global__ __launch_bounds__(256)
void k_convmma(const int* __restrict__ coords, const float* __restrict__ bias,
               const float* __restrict__ feats, float* __restrict__ dout) {
    extern __shared__ char dsm[];
    uint32_t smS = smem_u32(dsm);
    int* snb = (int*)(dsm + 3*STG_SZ);

    const __half* hsrc = ISC2 ? g_h2  : g_h1;
    const __half* Wp   = ISC2 ? g_W2h : g_M1h;
    float* outp        = ISC2 ? dout  : g_out1;

    int tid = threadIdx.x, lane = tid & 31, wid = tid >> 5;
    int wm = wid & 3, wn = wid >> 2;
    int bx = blockIdx.x, ko = blockIdx.y;
    const int matBase = ISC2 ? 0 : ko*8;

    // ---- neighbor precompute ----
    for (int t = tid; t < NTAPS*128; t += 256) {
        int tap = t >> 7, row = t & 127;
        int nb = -1;
        if (ISC2) {
            int grow = bx*128 + row;
            int pi = grow >> 3, k8 = grow & 7;
            int f0 = 2*coords[pi*3+0] + ((k8 >> 2) & 1) + (tap/9 - 1);
            int f1 = 2*coords[pi*3+1] + ((k8 >> 1) & 1) + ((tap/3) % 3 - 1);
            int f2 = 2*coords[pi*3+2] + (k8 & 1)        + (tap % 3 - 1);
            if ((unsigned)f0 < RESF && (unsigned)f1 < RESF && (unsigned)f2 < RESF) {
                int p = g_pg[((f0 >> 1)*RESP + (f1 >> 1))*RESP + (f2 >> 1)];
                if (p >= 0) nb = p*8 + (((f0 & 1) << 2) | ((f1 & 1) << 1) | (f2 & 1));
            }
        } else {
            int p = bx*128 + row;
            int q0 = coords[p*3+0] + ((ko >> 2) & 1) - 1 + ((tap >> 2) & 1);
            int q1 = coords[p*3+1] + ((ko >> 1) & 1) - 1 + ((tap >> 1) & 1);
            int q2 = coords[p*3+2] + (ko & 1)        - 1 + (tap & 1);
            if ((unsigned)q0 < RESP && (unsigned)q1 < RESP && (unsigned)q2 < RESP)
                nb = g_pg[(q0*RESP + q1)*RESP + q2];
        }
        snb[t] = nb;
    }
    __syncthreads();

    // loader: 2 threads/row; each covers 4x16B (=32 fp16) of A and of B
    const int lrow = tid >> 1, lhalf = tid & 1;
    const int lrx = lrow & 7;

    // per-lane ldmatrix constants (fp16 m16n8k16 fragment mapping)
    const int laneAr = (lane & 7) + ((lane >> 3) & 1)*8;
    const int laneAc = (lane >> 4) & 1;
    const int laneBr = (lane & 7) + ((lane >> 4) & 1)*8;
    const int laneBc = (lane >> 3) & 1;
    uint32_t offA[2], offB[4]; int rxA[2], rxB[4];
#pragma unroll
    for (int i = 0; i < 2; i++) {
        int rA = wm*32 + i*16 + laneAr;
        offA[i] = (uint32_t)rA * 128u; rxA[i] = rA & 7;
    }
#pragma unroll
    for (int i = 0; i < 4; i++) {
        int rB = wn*64 + i*16 + laneBr;
        offB[i] = 16384u + (uint32_t)rB * 128u; rxB[i] = rB & 7;
    }

    float acc[2][8][4];
#pragma unroll
    for (int mt = 0; mt < 2; mt++)
#pragma unroll
        for (int nt = 0; nt < 8; nt++)
#pragma unroll
            for (int c = 0; c < 4; c++) acc[mt][nt][c] = 0.f;

    const int T = NTAPS * 2;   // BK=64: 2 stages per tap

#define LOAD_STAGE(S, BUF) do { \
        int tap_ = (S) >> 1, c0_ = ((S) & 1) * 64; \
        int src_ = snb[tap_*128 + lrow]; \
        uint32_t ssz_ = src_ >= 0 ? 16u : 0u; \
        const __half* ap_ = hsrc + (src_ < 0 ? 0 : src_)*CH + c0_; \
        const __half* bp_ = Wp + ((matBase + tap_)*128 + lrow)*128 + c0_; \
        uint32_t ad_ = smS + (BUF)*STG_SZ + (uint32_t)lrow*128u; \
        uint32_t bd_ = ad_ + 16384u; \
        _Pragma("unroll") \
        for (int i_ = 0; i_ < 4; i_++) { \
            int c_ = lhalf*4 + i_; \
            uint32_t sw_ = (uint32_t)((c_ ^ lrx) << 4); \
            cp16(ad_ + sw_, ap_ + c_*8, ssz_); \
            cp16(bd_ + sw_, bp_ + c_*8, 16u); \
        } \
        cp_commit(); \
    } while (0)

    LOAD_STAGE(0, 0);
    LOAD_STAGE(1, 1);

    int sbuf = 0;
    for (int s = 0; s < T; s++) {
        if (s + 2 < T) CP_WAIT(1); else CP_WAIT(0);
        __syncthreads();
        if (s + 2 < T) {
            int buf2 = sbuf + 2; if (buf2 >= 3) buf2 -= 3;
            LOAD_STAGE(s + 2, buf2);
        }
        uint32_t stg = smS + (uint32_t)sbuf*STG_SZ;
#pragma unroll
        for (int ks = 0; ks < 4; ks++) {          // each ks = k16
            int cA = ks*2 + laneAc, cB = ks*2 + laneBc;
            uint32_t a[2][4];
            ldsm4(a[0], stg + offA[0] + (uint32_t)((cA ^ rxA[0]) << 4));
            ldsm4(a[1], stg + offA[1] + (uint32_t)((cA ^ rxA[1]) << 4));
            uint32_t b[4][4];
#pragma unroll
            for (int p = 0; p < 4; p++)
                ldsm4(b[p], stg + offB[p] + (uint32_t)((cB ^ rxB[p]) << 4));
#pragma unroll
            for (int mt = 0; mt < 2; mt++)
#pragma unroll
                for (int p = 0; p < 4; p++) {
                    mma_f16(acc[mt][p*2 + 0], a[mt], &b[p][0]);
                    mma_f16(acc[mt][p*2 + 1], a[mt], &b[p][2]);
                }
        }
        sbuf++; if (sbuf == 3) sbuf = 0;
    }
#undef LOAD_STAGE

    // ---- epilogue: register -> gmem, fused bias (+residual) ----
#pragma unroll
    for (int mt = 0; mt < 2; mt++) {
        int rl = wm*32 + mt*16 + (lane >> 2);
#pragma unroll
        for (int half = 0; half < 2; half++) {
            int row = rl + half*8;
            int orow, prow;
            if (ISC2) { orow = bx*128 + row; prow = orow >> 3; }
            else      { orow = (bx*128 + row)*8 + ko; prow = -1; }
#pragma unroll
            for (int nt = 0; nt < 8; nt++) {
                int col = wn*64 + nt*8 + (lane & 3)*2;
                float2 bb = *reinterpret_cast<const float2*>(bias + col);
                float vx = acc[mt][nt][half*2 + 0] + bb.x;
                float vy = acc[mt][nt][half*2 + 1] + bb.y;
                if (ISC2) {
                    float2 rr = *reinterpret_cast<const float2*>(feats + prow*CH + col);
                    vx += rr.x; vy += rr.y;
                }
                float2 o; o.x = vx; o.y = vy;
                *reinterpret_cast<float2*>(outp + orow*CH + col) = o;
            }
        }
    }
}

// ================= launch =================
extern "C" void kernel_launch(void* const* d_in, const int* in_sizes, int n_in,
                              void* d_out, int out_size) {
    const float* feats  = (const float*)d_in[0];
    const float* gamma1 = (const float*)d_in[1];
    const float* beta1  = (const float*)d_in[2];
    const float* W1     = (const float*)d_in[3];
    const float* b1     = (const float*)d_in[4];
    const float* gamma2 = (const float*)d_in[5];
    const float* beta2  = (const float*)d_in[6];
    const float* W2     = (const float*)d_in[7];
    const float* b2     = (const float*)d_in[8];
    const int*   coords = (const int*)d_in[9];
    float* out = (float*)d_out;

    const int smem1 = 3*STG_SZ + 8*128*4;    // 102400
    const int smem2 = 3*STG_SZ + 27*128*4;   // 112128
    cudaFuncSetAttribute(k_convmma<8,false>, cudaFuncAttributeMaxDynamicSharedMemorySize, smem1);
    cudaFuncSetAttribute(k_convmma<27,true>, cudaFuncAttributeMaxDynamicSharedMemorySize, smem2);

    // (0) grid build
    k_grid<<<1, 1024>>>(coords);
    // (1) weight prep -> fp16 [mat][n][k]
    k_prepw<<<(91*CH*CH + 255)/256, 256>>>(W1, W2);
    // (2) GN1 fused stats+norm+SiLU -> g_h1 (fp16)
    k_gn1<<<32, 256>>>(feats, gamma1, beta1);
    // (3) conv1 (parent-level, aggregated taps) -> g_out1 (fp32)   [ncu-profiled slot]
    k_convmma<8,false><<<dim3(64, 8), 256, smem1>>>(coords, b1, nullptr, nullptr);
    // (4,5) GN2 stats two-phase
    k_stats1<<<dim3(32, 32), 256>>>(32);
    k_stats2<<<32, 32>>>(32);
    // (6) GN2 normalize + SiLU -> g_h2 (fp16)
    k_gnsilu2<<<(NF*32 + 255)/256, 256>>>(gamma2, beta2);
    // (7) conv2 (fine-level, 27 taps) + bias + residual -> out
    k_convmma<27,true><<<512, 256, smem2>>>(coords, b2, feats, out);
}

// round 12
// speedup vs baseline: 3.0935x; 1.0312x over previous
#include <cuda_runtime.h>
#include <cuda_fp16.h>
#include <cstdint>

#define RESP 32
#define RESF 64
#define NP   8192
#define NF   65536
#define CH   128
#define EPSV 1e-5f

// ---- scratch (device globals: allocation-free rule) ----
__device__ int    g_pg[RESP*RESP*RESP];
__device__ __half g_h1[NP*CH];
__device__ float  g_out1[NF*CH];
__device__ __half g_h2[NF*CH];
__device__ __half g_M1h[64*CH*CH];   // aggregated conv1 weights, [mat][n][k], fp16
__device__ __half g_W2h[27*CH*CH];   // conv2 weights, [mat][n][k], fp16
__device__ float  g_sum[32], g_sq[32];      // GN2 stats
__device__ float  g_ps[32][32], g_pq[32][32];

// ================= helpers =================
__device__ __forceinline__ uint32_t smem_u32(const void* p) {
    uint32_t a;
    asm("{ .reg .u64 t; cvta.to.shared.u64 t, %1; cvt.u32.u64 %0, t; }" : "=r"(a) : "l"(p));
    return a;
}
__device__ __forceinline__ void cp16(uint32_t dst, const void* src, uint32_t ssz) {
    asm volatile("cp.async.cg.shared.global [%0], [%1], 16, %2;" :: "r"(dst), "l"(src), "r"(ssz));
}
__device__ __forceinline__ void cp_commit() { asm volatile("cp.async.commit_group;"); }
#define CP_WAIT(n) asm volatile("cp.async.wait_group %0;" :: "n"(n) : "memory")

__device__ __forceinline__ void ldsm4(uint32_t* r, uint32_t addr) {
    asm volatile("ldmatrix.sync.aligned.m8n8.x4.shared.b16 {%0,%1,%2,%3}, [%4];"
        : "=r"(r[0]), "=r"(r[1]), "=r"(r[2]), "=r"(r[3]) : "r"(addr));
}
// m16n8k16 fp16 MMA, fp32 accumulate
__device__ __forceinline__ void mma_f16(float* d, const uint32_t* a, const uint32_t* b) {
    asm volatile("mma.sync.aligned.m16n8k16.row.col.f32.f16.f16.f32 "
        "{%0,%1,%2,%3}, {%4,%5,%6,%7}, {%8,%9}, {%0,%1,%2,%3};"
        : "+f"(d[0]), "+f"(d[1]), "+f"(d[2]), "+f"(d[3])
        : "r"(a[0]), "r"(a[1]), "r"(a[2]), "r"(a[3]), "r"(b[0]), "r"(b[1]));
}
__device__ __forceinline__ void store_h4(__half* dst, float x, float y, float z, float w) {
    __half2 p0 = __floats2half2_rn(x, y);
    __half2 p1 = __floats2half2_rn(z, w);
    uint2 u;
    u.x = *reinterpret_cast<uint32_t*>(&p0);
    u.y = *reinterpret_cast<uint32_t*>(&p1);
    *reinterpret_cast<uint2*>(dst) = u;
}

// ================= fused grid build =================
__global__ __launch_bounds__(1024)
void k_grid(const int* __restrict__ coords) {
    int t = threadIdx.x;
    for (int i = t; i < RESP*RESP*RESP; i += 1024) g_pg[i] = -1;
    __syncthreads();
    for (int i = t; i < NP; i += 1024)
        g_pg[(coords[i*3]*RESP + coords[i*3+1])*RESP + coords[i*3+2]] = i;
}

// ================= fused weight prep (fp16 output, [mat][n][k]) =================
__global__ void k_prepw(const float* __restrict__ W1, const float* __restrict__ W2) {
    int idx = blockIdx.x * blockDim.x + threadIdx.x;
    if (idx < 64*CH*CH) {
        int m = idx >> 14, rest = idx & 16383;
        int n = rest >> 7, kk = rest & 127;
        int k = m >> 3, j = m & 7;
        int s[3], cnt[3];
#pragma unroll
        for (int a = 0; a < 3; a++) {
            int o  = (k >> (2 - a)) & 1;
            int eb = (j >> (2 - a)) & 1;
            cnt[a] = 1 + (o ^ eb);
            s[a]   = -1 + eb * (1 + o);
        }
        float acc = 0.f;
        for (int d0 = 0; d0 < cnt[0]; d0++)
            for (int d1 = 0; d1 < cnt[1]; d1++)
                for (int d2 = 0; d2 < cnt[2]; d2++) {
                    int k27 = ((s[0]+d0+1)*3 + (s[1]+d1+1))*3 + (s[2]+d2+1);
                    acc += W1[k27*CH*CH + kk*CH + n];
                }
        g_M1h[idx] = __float2half_rn(acc);
    } else if (idx < 91*CH*CH) {
        int i2 = idx - 64*CH*CH;
        int m = i2 >> 14, rest = i2 & 16383;
        int n = rest >> 7, kk = rest & 127;
        g_W2h[i2] = __float2half_rn(W2[m*CH*CH + kk*CH + n]);
    }
}

// ================= GN1: fused stats + normalize + SiLU -> fp16 =================
__global__ __launch_bounds__(256)
void k_gn1(const float* __restrict__ feats,
           const float* __restrict__ gamma, const float* __restrict__ beta) {
    int g = blockIdx.x, t = threadIdx.x;
    float s = 0.f, q = 0.f;
    for (int r = t; r < NP; r += 256) {
        float4 v = *reinterpret_cast<const float4*>(feats + r*CH + g*4);
        s += (v.x + v.y) + (v.z + v.w);
        q += (v.x*v.x + v.y*v.y) + (v.z*v.z + v.w*v.w);
    }
    __shared__ float ss[256], sq[256];
    ss[t] = s; sq[t] = q;
    __syncthreads();
    for (int st = 128; st > 0; st >>= 1) {
        if (t < st) { ss[t] += ss[t+st]; sq[t] += sq[t+st]; }
        __syncthreads();
    }
    const float invcnt = 1.f / (NP * 4);
    float mean = ss[0] * invcnt;
    float var  = sq[0] * invcnt - mean * mean;
    float inv  = rsqrtf(var + EPSV);
    float4 ga = *reinterpret_cast<const float4*>(gamma + g*4);
    float4 be = *reinterpret_cast<const float4*>(beta + g*4);
    for (int r = t; r < NP; r += 256) {
        float4 v = *reinterpret_cast<const float4*>(feats + r*CH + g*4);
        float y, ox, oy, oz, ow;
        y = (v.x - mean)*inv*ga.x + be.x; ox = y / (1.f + expf(-y));
        y = (v.y - mean)*inv*ga.y + be.y; oy = y / (1.f + expf(-y));
        y = (v.z - mean)*inv*ga.z + be.z; oz = y / (1.f + expf(-y));
        y = (v.w - mean)*inv*ga.w + be.w; ow = y / (1.f + expf(-y));
        store_h4(g_h1 + r*CH + g*4, ox, oy, oz, ow);
    }
}

// ================= GN2 stats (two-phase over fp32 g_out1) =================
__global__ void k_stats1(int nsl) {
    int g = blockIdx.x, sl = blockIdx.y;
    int per = NF / nsl, r0 = sl * per;
    float s = 0.f, q = 0.f;
    for (int r = r0 + threadIdx.x; r < r0 + per; r += blockDim.x) {
        float4 v = *reinterpret_cast<const float4*>(g_out1 + r*CH + g*4);
        s += (v.x + v.y) + (v.z + v.w);
        q += (v.x*v.x + v.y*v.y) + (v.z*v.z + v.w*v.w);
    }
    __shared__ float ss[256], sq[256];
    ss[threadIdx.x] = s; sq[threadIdx.x] = q;
    __syncthreads();
    for (int st = 128; st > 0; st >>= 1) {
        if (threadIdx.x < st) { ss[threadIdx.x] += ss[threadIdx.x+st]; sq[threadIdx.x] += sq[threadIdx.x+st]; }
        __syncthreads();
    }
    if (threadIdx.x == 0) { g_ps[g][sl] = ss[0]; g_pq[g][sl] = sq[0]; }
}
__global__ void k_stats2(int nsl) {
    int g = blockIdx.x, t = threadIdx.x;
    float s = (t < nsl) ? g_ps[g][t] : 0.f;
    float q = (t < nsl) ? g_pq[g][t] : 0.f;
#pragma unroll
    for (int o = 16; o > 0; o >>= 1) {
        s += __shfl_xor_sync(0xffffffff, s, o);
        q += __shfl_xor_sync(0xffffffff, q, o);
    }
    if (t == 0) { g_sum[g] = s; g_sq[g] = q; }
}
__global__ void k_gnsilu2(const float* __restrict__ gamma, const float* __restrict__ beta) {
    int idx = blockIdx.x * blockDim.x + threadIdx.x;
    if (idx >= NF*32) return;
    int g = idx & 31;
    const float invcnt = 1.f / (NF * 4);
    float mean = g_sum[g] * invcnt;
    float var  = g_sq[g] * invcnt - mean * mean;
    float inv  = rsqrtf(var + EPSV);
    float4 v  = reinterpret_cast<const float4*>(g_out1)[idx];
    float4 ga = reinterpret_cast<const float4*>(gamma)[g];
    float4 be = reinterpret_cast<const float4*>(beta)[g];
    float y, ox, oy, oz, ow;
    y = (v.x - mean)*inv*ga.x + be.x; ox = y / (1.f + expf(-y));
    y = (v.y - mean)*inv*ga.y + be.y; oy = y / (1.f + expf(-y));
    y = (v.z - mean)*inv*ga.z + be.z; oz = y / (1.f + expf(-y));
    y = (v.w - mean)*inv*ga.w + be.w; ow = y / (1.f + expf(-y));
    store_h4(g_h2 + idx*4, ox, oy, oz, ow);
}

// ================= fp16 mma conv kernels =================
// CTA 128x128, 8 warps (4m x 2n), warp tile 32x64.
// BK=64 channels per stage (128B fp16 rows), XOR-swizzled, 3-stage cp.async.
// Fragments double-buffered across ks: ks+1's LDSMs issue before ks's MMAs,
// so the MMA burst covers LDSM latency. regs capped at 128 (2 CTA/SM).
#define STG_SZ 32768         // A 16KB + B 16KB per stage

template<int NTAPS, bool ISC2>
__global__ __launch_bounds__(256, 2)
void k_convmma(const int* __restrict__ coords, const float* __restrict__ bias,
               const float* __restrict__ feats, float* __restrict__ dout) {
    extern __shared__ char dsm[];
    uint32_t smS = smem_u32(dsm);
    int* snb = (int*)(dsm + 3*STG_SZ);

    const __half* hsrc = ISC2 ? g_h2  : g_h1;
    const __half* Wp   = ISC2 ? g_W2h : g_M1h;
    float* outp        = ISC2 ? dout  : g_out1;

    int tid = threadIdx.x, lane = tid & 31, wid = tid >> 5;
    int wm = wid & 3, wn = wid >> 2;
    int bx = blockIdx.x, ko = blockIdx.y;
    const int matBase = ISC2 ? 0 : ko*8;

    // ---- neighbor precompute ----
    for (int t = tid; t < NTAPS*128; t += 256) {
        int tap = t >> 7, row = t & 127;
        int nb = -1;
        if (ISC2) {
            int grow = bx*128 + row;
            int pi = grow >> 3, k8 = grow & 7;
            int f0 = 2*coords[pi*3+0] + ((k8 >> 2) & 1) + (tap/9 - 1);
            int f1 = 2*coords[pi*3+1] + ((k8 >> 1) & 1) + ((tap/3) % 3 - 1);
            int f2 = 2*coords[pi*3+2] + (k8 & 1)        + (tap % 3 - 1);
            if ((unsigned)f0 < RESF && (unsigned)f1 < RESF && (unsigned)f2 < RESF) {
                int p = g_pg[((f0 >> 1)*RESP + (f1 >> 1))*RESP + (f2 >> 1)];
                if (p >= 0) nb = p*8 + (((f0 & 1) << 2) | ((f1 & 1) << 1) | (f2 & 1));
            }
        } else {
            int p = bx*128 + row;
            int q0 = coords[p*3+0] + ((ko >> 2) & 1) - 1 + ((tap >> 2) & 1);
            int q1 = coords[p*3+1] + ((ko >> 1) & 1) - 1 + ((tap >> 1) & 1);
            int q2 = coords[p*3+2] + (ko & 1)        - 1 + (tap & 1);
            if ((unsigned)q0 < RESP && (unsigned)q1 < RESP && (unsigned)q2 < RESP)
                nb = g_pg[(q0*RESP + q1)*RESP + q2];
        }
        snb[t] = nb;
    }
    __syncthreads();

    // loader: 2 threads/row; each covers 4x16B (=32 fp16) of A and of B
    const int lrow = tid >> 1, lhalf = tid & 1;
    const int lrx = lrow & 7;

    // per-lane ldmatrix constants (fp16 m16n8k16 fragment mapping)
    const int laneAr = (lane & 7) + ((lane >> 3) & 1)*8;
    const int laneAc = (lane >> 4) & 1;
    const int laneBr = (lane & 7) + ((lane >> 4) & 1)*8;
    const int laneBc = (lane >> 3) & 1;
    uint32_t offA[2], offB[4]; int rxA[2], rxB[4];
#pragma unroll
    for (int i = 0; i < 2; i++) {
        int rA = wm*32 + i*16 + laneAr;
        offA[i] = (uint32_t)rA * 128u; rxA[i] = rA & 7;
    }
#pragma unroll
    for (int i = 0; i < 4; i++) {
        int rB = wn*64 + i*16 + laneBr;
        offB[i] = 16384u + (uint32_t)rB * 128u; rxB[i] = rB & 7;
    }

    float acc[2][8][4];
#pragma unroll
    for (int mt = 0; mt < 2; mt++)
#pragma unroll
        for (int nt = 0; nt < 8; nt++)
#pragma unroll
            for (int c = 0; c < 4; c++) acc[mt][nt][c] = 0.f;

    const int T = NTAPS * 2;   // BK=64: 2 stages per tap

#define LOAD_STAGE(S, BUF) do { \
        int tap_ = (S) >> 1, c0_ = ((S) & 1) * 64; \
        int src_ = snb[tap_*128 + lrow]; \
        uint32_t ssz_ = src_ >= 0 ? 16u : 0u; \
        const __half* ap_ = hsrc + (src_ < 0 ? 0 : src_)*CH + c0_; \
        const __half* bp_ = Wp + ((matBase + tap_)*128 + lrow)*128 + c0_; \
        uint32_t ad_ = smS + (BUF)*STG_SZ + (uint32_t)lrow*128u; \
        uint32_t bd_ = ad_ + 16384u; \
        _Pragma("unroll") \
        for (int i_ = 0; i_ < 4; i_++) { \
            int c_ = lhalf*4 + i_; \
            uint32_t sw_ = (uint32_t)((c_ ^ lrx) << 4); \
            cp16(ad_ + sw_, ap_ + c_*8, ssz_); \
            cp16(bd_ + sw_, bp_ + c_*8, 16u); \
        } \
        cp_commit(); \
    } while (0)

// load fragments for k16-index KS of current stage into frag buffer FB
#define LOAD_FRAGS(stg_, KS, FB) do { \
        int cA_ = (KS)*2 + laneAc, cB_ = (KS)*2 + laneBc; \
        ldsm4(a[FB][0], (stg_) + offA[0] + (uint32_t)((cA_ ^ rxA[0]) << 4)); \
        ldsm4(a[FB][1], (stg_) + offA[1] + (uint32_t)((cA_ ^ rxA[1]) << 4)); \
        _Pragma("unroll") \
        for (int p_ = 0; p_ < 4; p_++) \
            ldsm4(b[FB][p_], (stg_) + offB[p_] + (uint32_t)((cB_ ^ rxB[p_]) << 4)); \
    } while (0)

#define DO_MMAS(FB) do { \
        _Pragma("unroll") \
        for (int mt_ = 0; mt_ < 2; mt_++) \
            _Pragma("unroll") \
            for (int p_ = 0; p_ < 4; p_++) { \
                mma_f16(acc[mt_][p_*2 + 0], a[FB][mt_], &b[FB][p_][0]); \
                mma_f16(acc[mt_][p_*2 + 1], a[FB][mt_], &b[FB][p_][2]); \
            } \
    } while (0)

    LOAD_STAGE(0, 0);
    LOAD_STAGE(1, 1);

    uint32_t a[2][2][4], b[2][4][4];   // double-buffered fragments

    int sbuf = 0;
    for (int s = 0; s < T; s++) {
        if (s + 2 < T) CP_WAIT(1); else CP_WAIT(0);
        __syncthreads();
        if (s + 2 < T) {
            int buf2 = sbuf + 2; if (buf2 >= 3) buf2 -= 3;
            LOAD_STAGE(s + 2, buf2);
        }
        uint32_t stg = smS + (uint32_t)sbuf*STG_SZ;
        LOAD_FRAGS(stg, 0, 0);
#pragma unroll
        for (int ks = 0; ks < 4; ks++) {
            int cur = ks & 1;
            if (ks < 3) LOAD_FRAGS(stg, ks + 1, cur ^ 1);
            DO_MMAS(cur);
        }
        sbuf++; if (sbuf == 3) sbuf = 0;
    }
#undef LOAD_STAGE
#undef LOAD_FRAGS
#undef DO_MMAS

    // ---- epilogue: register -> gmem, fused bias (+residual) ----
#pragma unroll
    for (int mt = 0; mt < 2; mt++) {
        int rl = wm*32 + mt*16 + (lane >> 2);
#pragma unroll
        for (int half = 0; half < 2; half++) {
            int row = rl + half*8;
            int orow, prow;
            if (ISC2) { orow = bx*128 + row; prow = orow >> 3; }
            else      { orow = (bx*128 + row)*8 + ko; prow = -1; }
#pragma unroll
            for (int nt = 0; nt < 8; nt++) {
                int col = wn*64 + nt*8 + (lane & 3)*2;
                float2 bb = *reinterpret_cast<const float2*>(bias + col);
                float vx = acc[mt][nt][half*2 + 0] + bb.x;
                float vy = acc[mt][nt][half*2 + 1] + bb.y;
                if (ISC2) {
                    float2 rr = *reinterpret_cast<const float2*>(feats + prow*CH + col);
                    vx += rr.x; vy += rr.y;
                }
                float2 o; o.x = vx; o.y = vy;
                *reinterpret_cast<float2*>(outp + orow*CH + col) = o;
            }
        }
    }
}

// ================= launch =================
extern "C" void kernel_launch(void* const* d_in, const int* in_sizes, int n_in,
                              void* d_out, int out_size) {
    const float* feats  = (const float*)d_in[0];
    const float* gamma1 = (const float*)d_in[1];
    const float* beta1  = (const float*)d_in[2];
    const float* W1     = (const float*)d_in[3];
    const float* b1     = (const float*)d_in[4];
    const float* gamma2 = (const float*)d_in[5];
    const float* beta2  = (const float*)d_in[6];
    const float* W2     = (const float*)d_in[7];
    const float* b2     = (const float*)d_in[8];
    const int*   coords = (const int*)d_in[9];
    float* out = (float*)d_out;

    const int smem1 = 3*STG_SZ + 8*128*4;    // 102400
    const int smem2 = 3*STG_SZ + 27*128*4;   // 112128
    cudaFuncSetAttribute(k_convmma<8,false>, cudaFuncAttributeMaxDynamicSharedMemorySize, smem1);
    cudaFuncSetAttribute(k_convmma<27,true>, cudaFuncAttributeMaxDynamicSharedMemorySize, smem2);

    // (0) grid build
    k_grid<<<1, 1024>>>(coords);
    // (1) weight prep -> fp16 [mat][n][k]
    k_prepw<<<(91*CH*CH + 255)/256, 256>>>(W1, W2);
    // (2) GN1 fused stats+norm+SiLU -> g_h1 (fp16)
    k_gn1<<<32, 256>>>(feats, gamma1, beta1);
    // (3) conv1 (parent-level, aggregated taps) -> g_out1 (fp32)   [ncu-profiled slot]
    k_convmma<8,false><<<dim3(64, 8), 256, smem1>>>(coords, b1, nullptr, nullptr);
    // (4,5) GN2 stats two-phase
    k_stats1<<<dim3(32, 32), 256>>>(32);
    k_stats2<<<32, 32>>>(32);
    // (6) GN2 normalize + SiLU -> g_h2 (fp16)
    k_gnsilu2<<<(NF*32 + 255)/256, 256>>>(gamma2, beta2);
    // (7) conv2 (fine-level, 27 taps) + bias + residual -> out
    k_convmma<27,true><<<512, 256, smem2>>>(coords, b2, feats, out);
}

// round 13
// speedup vs baseline: 3.2017x; 1.0350x over previous
#include <cuda_runtime.h>
#include <cuda_fp16.h>
#include <cstdint>

#define RESP 32
#define RESF 64
#define NP   8192
#define NF   65536
#define CH   128
#define EPSV 1e-5f

// ---- scratch (device globals: allocation-free rule) ----
__device__ int    g_pg[RESP*RESP*RESP];
__device__ __half g_h1[NP*CH];
__device__ float  g_out1[NF*CH];
__device__ __half g_h2[NF*CH];
__device__ __half g_M1h[64*CH*CH];   // aggregated conv1 weights, [mat][n][k], fp16
__device__ __half g_W2h[27*CH*CH];   // conv2 weights, [mat][n][k], fp16
__device__ float  g_sum[32], g_sq[32];      // GN2 stats
__device__ float  g_ps[32][32], g_pq[32][32];

// ================= helpers =================
__device__ __forceinline__ uint32_t smem_u32(const void* p) {
    uint32_t a;
    asm("{ .reg .u64 t; cvta.to.shared.u64 t, %1; cvt.u32.u64 %0, t; }" : "=r"(a) : "l"(p));
    return a;
}
__device__ __forceinline__ void cp16(uint32_t dst, const void* src, uint32_t ssz) {
    asm volatile("cp.async.cg.shared.global [%0], [%1], 16, %2;" :: "r"(dst), "l"(src), "r"(ssz));
}
__device__ __forceinline__ void cp_commit() { asm volatile("cp.async.commit_group;"); }
#define CP_WAIT(n) asm volatile("cp.async.wait_group %0;" :: "n"(n) : "memory")

__device__ __forceinline__ void ldsm4(uint32_t* r, uint32_t addr) {
    asm volatile("ldmatrix.sync.aligned.m8n8.x4.shared.b16 {%0,%1,%2,%3}, [%4];"
        : "=r"(r[0]), "=r"(r[1]), "=r"(r[2]), "=r"(r[3]) : "r"(addr));
}
// m16n8k16 fp16 MMA, fp32 accumulate
__device__ __forceinline__ void mma_f16(float* d, const uint32_t* a, const uint32_t* b) {
    asm volatile("mma.sync.aligned.m16n8k16.row.col.f32.f16.f16.f32 "
        "{%0,%1,%2,%3}, {%4,%5,%6,%7}, {%8,%9}, {%0,%1,%2,%3};"
        : "+f"(d[0]), "+f"(d[1]), "+f"(d[2]), "+f"(d[3])
        : "r"(a[0]), "r"(a[1]), "r"(a[2]), "r"(a[3]), "r"(b[0]), "r"(b[1]));
}
__device__ __forceinline__ void store_h4(__half* dst, float x, float y, float z, float w) {
    __half2 p0 = __floats2half2_rn(x, y);
    __half2 p1 = __floats2half2_rn(z, w);
    uint2 u;
    u.x = *reinterpret_cast<uint32_t*>(&p0);
    u.y = *reinterpret_cast<uint32_t*>(&p1);
    *reinterpret_cast<uint2*>(dst) = u;
}

// ================= fused grid build =================
__global__ __launch_bounds__(1024)
void k_grid(const int* __restrict__ coords) {
    int t = threadIdx.x;
    for (int i = t; i < RESP*RESP*RESP; i += 1024) g_pg[i] = -1;
    __syncthreads();
    for (int i = t; i < NP; i += 1024)
        g_pg[(coords[i*3]*RESP + coords[i*3+1])*RESP + coords[i*3+2]] = i;
}

// ================= fused weight prep (fp16 output, [mat][n][k]) =================
__global__ void k_prepw(const float* __restrict__ W1, const float* __restrict__ W2) {
    int idx = blockIdx.x * blockDim.x + threadIdx.x;
    if (idx < 64*CH*CH) {
        int m = idx >> 14, rest = idx & 16383;
        int n = rest >> 7, kk = rest & 127;
        int k = m >> 3, j = m & 7;
        int s[3], cnt[3];
#pragma unroll
        for (int a = 0; a < 3; a++) {
            int o  = (k >> (2 - a)) & 1;
            int eb = (j >> (2 - a)) & 1;
            cnt[a] = 1 + (o ^ eb);
            s[a]   = -1 + eb * (1 + o);
        }
        float acc = 0.f;
        for (int d0 = 0; d0 < cnt[0]; d0++)
            for (int d1 = 0; d1 < cnt[1]; d1++)
                for (int d2 = 0; d2 < cnt[2]; d2++) {
                    int k27 = ((s[0]+d0+1)*3 + (s[1]+d1+1))*3 + (s[2]+d2+1);
                    acc += W1[k27*CH*CH + kk*CH + n];
                }
        g_M1h[idx] = __float2half_rn(acc);
    } else if (idx < 91*CH*CH) {
        int i2 = idx - 64*CH*CH;
        int m = i2 >> 14, rest = i2 & 16383;
        int n = rest >> 7, kk = rest & 127;
        g_W2h[i2] = __float2half_rn(W2[m*CH*CH + kk*CH + n]);
    }
}

// ================= GN1: fused stats + normalize + SiLU -> fp16 =================
__global__ __launch_bounds__(256)
void k_gn1(const float* __restrict__ feats,
           const float* __restrict__ gamma, const float* __restrict__ beta) {
    int g = blockIdx.x, t = threadIdx.x;
    float s = 0.f, q = 0.f;
    for (int r = t; r < NP; r += 256) {
        float4 v = *reinterpret_cast<const float4*>(feats + r*CH + g*4);
        s += (v.x + v.y) + (v.z + v.w);
        q += (v.x*v.x + v.y*v.y) + (v.z*v.z + v.w*v.w);
    }
    __shared__ float ss[256], sq[256];
    ss[t] = s; sq[t] = q;
    __syncthreads();
    for (int st = 128; st > 0; st >>= 1) {
        if (t < st) { ss[t] += ss[t+st]; sq[t] += sq[t+st]; }
        __syncthreads();
    }
    const float invcnt = 1.f / (NP * 4);
    float mean = ss[0] * invcnt;
    float var  = sq[0] * invcnt - mean * mean;
    float inv  = rsqrtf(var + EPSV);
    float4 ga = *reinterpret_cast<const float4*>(gamma + g*4);
    float4 be = *reinterpret_cast<const float4*>(beta + g*4);
    for (int r = t; r < NP; r += 256) {
        float4 v = *reinterpret_cast<const float4*>(feats + r*CH + g*4);
        float y, ox, oy, oz, ow;
        y = (v.x - mean)*inv*ga.x + be.x; ox = y / (1.f + expf(-y));
        y = (v.y - mean)*inv*ga.y + be.y; oy = y / (1.f + expf(-y));
        y = (v.z - mean)*inv*ga.z + be.z; oz = y / (1.f + expf(-y));
        y = (v.w - mean)*inv*ga.w + be.w; ow = y / (1.f + expf(-y));
        store_h4(g_h1 + r*CH + g*4, ox, oy, oz, ow);
    }
}

// ================= GN2 stats (two-phase over fp32 g_out1) =================
__global__ void k_stats1(int nsl) {
    int g = blockIdx.x, sl = blockIdx.y;
    int per = NF / nsl, r0 = sl * per;
    float s = 0.f, q = 0.f;
    for (int r = r0 + threadIdx.x; r < r0 + per; r += blockDim.x) {
        float4 v = *reinterpret_cast<const float4*>(g_out1 + r*CH + g*4);
        s += (v.x + v.y) + (v.z + v.w);
        q += (v.x*v.x + v.y*v.y) + (v.z*v.z + v.w*v.w);
    }
    __shared__ float ss[256], sq[256];
    ss[threadIdx.x] = s; sq[threadIdx.x] = q;
    __syncthreads();
    for (int st = 128; st > 0; st >>= 1) {
        if (threadIdx.x < st) { ss[threadIdx.x] += ss[threadIdx.x+st]; sq[threadIdx.x] += sq[threadIdx.x+st]; }
        __syncthreads();
    }
    if (threadIdx.x == 0) { g_ps[g][sl] = ss[0]; g_pq[g][sl] = sq[0]; }
}
__global__ void k_stats2(int nsl) {
    int g = blockIdx.x, t = threadIdx.x;
    float s = (t < nsl) ? g_ps[g][t] : 0.f;
    float q = (t < nsl) ? g_pq[g][t] : 0.f;
#pragma unroll
    for (int o = 16; o > 0; o >>= 1) {
        s += __shfl_xor_sync(0xffffffff, s, o);
        q += __shfl_xor_sync(0xffffffff, q, o);
    }
    if (t == 0) { g_sum[g] = s; g_sq[g] = q; }
}
__global__ void k_gnsilu2(const float* __restrict__ gamma, const float* __restrict__ beta) {
    int idx = blockIdx.x * blockDim.x + threadIdx.x;
    if (idx >= NF*32) return;
    int g = idx & 31;
    const float invcnt = 1.f / (NF * 4);
    float mean = g_sum[g] * invcnt;
    float var  = g_sq[g] * invcnt - mean * mean;
    float inv  = rsqrtf(var + EPSV);
    float4 v  = reinterpret_cast<const float4*>(g_out1)[idx];
    float4 ga = reinterpret_cast<const float4*>(gamma)[g];
    float4 be = reinterpret_cast<const float4*>(beta)[g];
    float y, ox, oy, oz, ow;
    y = (v.x - mean)*inv*ga.x + be.x; ox = y / (1.f + expf(-y));
    y = (v.y - mean)*inv*ga.y + be.y; oy = y / (1.f + expf(-y));
    y = (v.z - mean)*inv*ga.z + be.z; oz = y / (1.f + expf(-y));
    y = (v.w - mean)*inv*ga.w + be.w; ow = y / (1.f + expf(-y));
    store_h4(g_h2 + idx*4, ox, oy, oz, ow);
}

// ================= fp16 mma conv kernels =================
// CTA 64 rows x 128 cols, 8 warps (2m x 4n), warp tile 32x32 -> acc=32 regs.
// BK=64 fp16 per stage; stage = A 8KB + B 16KB = 24KB. PD-stage cp.async.
// __launch_bounds__(256,3): 3 CTAs/SM = 24 warps (live set ~75 regs, cap 85).
#define STG_SZ 24576
#define TM 64

template<int NTAPS, int PD, bool ISC2>
__global__ __launch_bounds__(256, 3)
void k_convmma(const int* __restrict__ coords, const float* __restrict__ bias,
               const float* __restrict__ feats, float* __restrict__ dout) {
    extern __shared__ char dsm[];
    uint32_t smS = smem_u32(dsm);
    int* snb = (int*)(dsm + PD*STG_SZ);

    const __half* hsrc = ISC2 ? g_h2  : g_h1;
    const __half* Wp   = ISC2 ? g_W2h : g_M1h;
    float* outp        = ISC2 ? dout  : g_out1;

    int tid = threadIdx.x, lane = tid & 31, wid = tid >> 5;
    int wm = wid >> 2, wn = wid & 3;          // 2m x 4n
    int bx = blockIdx.x, ko = blockIdx.y;
    const int matBase = ISC2 ? 0 : ko*8;

    // ---- neighbor precompute (TM=64 rows) ----
    for (int t = tid; t < NTAPS*TM; t += 256) {
        int tap = t >> 6, row = t & (TM-1);
        int nb = -1;
        if (ISC2) {
            int grow = bx*TM + row;
            int pi = grow >> 3, k8 = grow & 7;
            int f0 = 2*coords[pi*3+0] + ((k8 >> 2) & 1) + (tap/9 - 1);
            int f1 = 2*coords[pi*3+1] + ((k8 >> 1) & 1) + ((tap/3) % 3 - 1);
            int f2 = 2*coords[pi*3+2] + (k8 & 1)        + (tap % 3 - 1);
            if ((unsigned)f0 < RESF && (unsigned)f1 < RESF && (unsigned)f2 < RESF) {
                int p = g_pg[((f0 >> 1)*RESP + (f1 >> 1))*RESP + (f2 >> 1)];
                if (p >= 0) nb = p*8 + (((f0 & 1) << 2) | ((f1 & 1) << 1) | (f2 & 1));
            }
        } else {
            int p = bx*TM + row;
            int q0 = coords[p*3+0] + ((ko >> 2) & 1) - 1 + ((tap >> 2) & 1);
            int q1 = coords[p*3+1] + ((ko >> 1) & 1) - 1 + ((tap >> 1) & 1);
            int q2 = coords[p*3+2] + (ko & 1)        - 1 + (tap & 1);
            if ((unsigned)q0 < RESP && (unsigned)q1 < RESP && (unsigned)q2 < RESP)
                nb = g_pg[(q0*RESP + q1)*RESP + q2];
        }
        snb[t] = nb;
    }
    __syncthreads();

    // loaders: A 64 rows x 8 chunks -> 4 threads/row, 2 cp16 each;
    //          B 128 rows x 8 chunks -> 2 threads/row, 4 cp16 each
    const int ar = tid >> 2, ac0 = (tid & 3) * 2, arx = ar & 7;
    const int br = tid >> 1, bh = tid & 1,       brx = br & 7;

    // ldsm lane constants (m16n8k16 fragment mapping)
    const int laneAr = (lane & 7) + ((lane >> 3) & 1)*8;
    const int laneAc = (lane >> 4) & 1;
    const int laneBr = (lane & 7) + ((lane >> 4) & 1)*8;
    const int laneBc = (lane >> 3) & 1;
    uint32_t offA[2], offB[2]; int rxA[2], rxB[2];
#pragma unroll
    for (int i = 0; i < 2; i++) {
        int rA = wm*32 + i*16 + laneAr;
        offA[i] = (uint32_t)rA * 128u; rxA[i] = rA & 7;
        int rB = wn*32 + i*16 + laneBr;
        offB[i] = 8192u + (uint32_t)rB * 128u; rxB[i] = rB & 7;
    }

    float acc[2][4][4];
#pragma unroll
    for (int mt = 0; mt < 2; mt++)
#pragma unroll
        for (int nt = 0; nt < 4; nt++)
#pragma unroll
            for (int c = 0; c < 4; c++) acc[mt][nt][c] = 0.f;

    const int T = NTAPS * 2;   // BK=64: 2 stages per tap

#define LOAD_STAGE(S, BUF) do { \
        int tap_ = (S) >> 1, c0_ = ((S) & 1) * 64; \
        uint32_t base_ = smS + (BUF)*STG_SZ; \
        { \
            int src_ = snb[tap_*TM + ar]; \
            uint32_t ssz_ = src_ >= 0 ? 16u : 0u; \
            const __half* ap_ = hsrc + (src_ < 0 ? 0 : src_)*CH + c0_; \
            uint32_t ad_ = base_ + (uint32_t)ar*128u; \
            _Pragma("unroll") \
            for (int i_ = 0; i_ < 2; i_++) { \
                int c_ = ac0 + i_; \
                cp16(ad_ + (uint32_t)((c_ ^ arx) << 4), ap_ + c_*8, ssz_); \
            } \
        } \
        { \
            const __half* bp_ = Wp + ((matBase + tap_)*128 + br)*128 + c0_; \
            uint32_t bd_ = base_ + 8192u + (uint32_t)br*128u; \
            _Pragma("unroll") \
            for (int i_ = 0; i_ < 4; i_++) { \
                int c_ = bh*4 + i_; \
                cp16(bd_ + (uint32_t)((c_ ^ brx) << 4), bp_ + c_*8, 16u); \
            } \
        } \
        cp_commit(); \
    } while (0)

    // prologue: stages 0..PD-2
#pragma unroll
    for (int s = 0; s < PD - 1; s++) LOAD_STAGE(s, s);

    int sbuf = 0;
    for (int s = 0; s < T; s++) {
        if (s + PD - 1 < T) CP_WAIT(PD - 2); else CP_WAIT(0);
        __syncthreads();
        if (s + PD - 1 < T) {
            int bufn = sbuf + PD - 1; if (bufn >= PD) bufn -= PD;
            LOAD_STAGE(s + PD - 1, bufn);
        }
        uint32_t stg = smS + (uint32_t)sbuf*STG_SZ;
#pragma unroll
        for (int ks = 0; ks < 4; ks++) {
            int cA = ks*2 + laneAc, cB = ks*2 + laneBc;
            uint32_t a[2][4], b[2][4];
            ldsm4(a[0], stg + offA[0] + (uint32_t)((cA ^ rxA[0]) << 4));
            ldsm4(a[1], stg + offA[1] + (uint32_t)((cA ^ rxA[1]) << 4));
            ldsm4(b[0], stg + offB[0] + (uint32_t)((cB ^ rxB[0]) << 4));
            ldsm4(b[1], stg + offB[1] + (uint32_t)((cB ^ rxB[1]) << 4));
#pragma unroll
            for (int mt = 0; mt < 2; mt++)
#pragma unroll
                for (int nt = 0; nt < 4; nt++)
                    mma_f16(acc[mt][nt], a[mt], &b[nt >> 1][(nt & 1)*2]);
        }
        sbuf++; if (sbuf == PD) sbuf = 0;
    }
#undef LOAD_STAGE

    // ---- epilogue: register -> gmem, fused bias (+residual) ----
#pragma unroll
    for (int mt = 0; mt < 2; mt++) {
        int rl = wm*32 + mt*16 + (lane >> 2);
#pragma unroll
        for (int half = 0; half < 2; half++) {
            int row = rl + half*8;
            int orow, prow;
            if (ISC2) { orow = bx*TM + row; prow = orow >> 3; }
            else      { orow = (bx*TM + row)*8 + ko; prow = -1; }
#pragma unroll
            for (int nt = 0; nt < 4; nt++) {
                int col = wn*32 + nt*8 + (lane & 3)*2;
                float2 bb = *reinterpret_cast<const float2*>(bias + col);
                float vx = acc[mt][nt][half*2 + 0] + bb.x;
                float vy = acc[mt][nt][half*2 + 1] + bb.y;
                if (ISC2) {
                    float2 rr = *reinterpret_cast<const float2*>(feats + prow*CH + col);
                    vx += rr.x; vy += rr.y;
                }
                float2 o; o.x = vx; o.y = vy;
                *reinterpret_cast<float2*>(outp + orow*CH + col) = o;
            }
        }
    }
}

// ================= launch =================
extern "C" void kernel_launch(void* const* d_in, const int* in_sizes, int n_in,
                              void* d_out, int out_size) {
    const float* feats  = (const float*)d_in[0];
    const float* gamma1 = (const float*)d_in[1];
    const float* beta1  = (const float*)d_in[2];
    const float* W1     = (const float*)d_in[3];
    const float* b1     = (const float*)d_in[4];
    const float* gamma2 = (const float*)d_in[5];
    const float* beta2  = (const float*)d_in[6];
    const float* W2     = (const float*)d_in[7];
    const float* b2     = (const float*)d_in[8];
    const int*   coords = (const int*)d_in[9];
    float* out = (float*)d_out;

    const int smem1 = 3*STG_SZ + 8*TM*4;     // 75776  (PD=3)
    const int smem2 = 2*STG_SZ + 27*TM*4;    // 56064  (PD=2)
    cudaFuncSetAttribute(k_convmma<8,3,false>, cudaFuncAttributeMaxDynamicSharedMemorySize, smem1);
    cudaFuncSetAttribute(k_convmma<27,2,true>, cudaFuncAttributeMaxDynamicSharedMemorySize, smem2);

    // (0) grid build
    k_grid<<<1, 1024>>>(coords);
    // (1) weight prep -> fp16 [mat][n][k]
    k_prepw<<<(91*CH*CH + 255)/256, 256>>>(W1, W2);
    // (2) GN1 fused stats+norm+SiLU -> g_h1 (fp16)
    k_gn1<<<32, 256>>>(feats, gamma1, beta1);
    // (3) conv1 (parent-level, aggregated taps) -> g_out1 (fp32)   [ncu-profiled slot]
    k_convmma<8,3,false><<<dim3(NP/TM, 8), 256, smem1>>>(coords, b1, nullptr, nullptr);
    // (4,5) GN2 stats two-phase
    k_stats1<<<dim3(32, 32), 256>>>(32);
    k_stats2<<<32, 32>>>(32);
    // (6) GN2 normalize + SiLU -> g_h2 (fp16)
    k_gnsilu2<<<(NF*32 + 255)/256, 256>>>(gamma2, beta2);
    // (7) conv2 (fine-level, 27 taps) + bias + residual -> out
    k_convmma<27,2,true><<<NF/TM, 256, smem2>>>(coords, b2, feats, out);
}